// round 13
// baseline (speedup 1.0000x reference)
#include <cuda_runtime.h>
#include <cuda_bf16.h>
#include <cstdint>
#include <math.h>

#define B_   32
#define T_   1600
#define E_   1024
#define D_   1024
#define A_   512
#define C_   10
#define KW   201
#define FILTR 100

// output layout: ctx (B,E), w (B,T), h_new (B,A), c_new (B,A)
#define OUT_CTX 0
#define OUT_W   (B_*E_)
#define OUT_H   (OUT_W + B_*T_)
#define OUT_CN  (OUT_H + B_*A_)

// GEMM tiling: CTA 128(t) x 256(a), 8 warps (2m x 4n), warp tile 64x64
#define MT   128
#define NT   256
#define KC   32
#define NKT  (E_/KC)              // 32
#define MTILES ((T_ + MT - 1)/MT) // 13

// stage: Ah 8K | Al 8K | Bh 16K | Bl 16K = 48KB; 3 stages = 144KB
#define STAGE_B 49152u
#define SMEM_DYN 147456

// mega_pre block ranges
#define NB_SPLIT 4096
#define NB_CONV  (B_*C_)
#define NB_GATES 640

// -------- scratch --------
__device__ __nv_bfloat16 g_eh[(size_t)(B_*T_ + MT) * E_];
__device__ __nv_bfloat16 g_el[(size_t)(B_*T_ + MT) * E_];
__device__ __nv_bfloat16 g_wh[(size_t)A_ * E_];
__device__ __nv_bfloat16 g_wl[(size_t)A_ * E_];
__device__ float g_feat[B_*C_];
__device__ float g_gates[B_*4*A_];   // W_hh@h part only
__device__ float g_dp[B_*A_];
__device__ float g_e[B_*T_];

static __device__ __forceinline__ float sigmf(float x){ return 1.0f/(1.0f+expf(-x)); }
static __device__ __forceinline__ unsigned smem_u32(const void* p){
    return (unsigned)__cvta_generic_to_shared(p);
}
static __device__ __forceinline__ void cp16(unsigned d, const void* s){
    asm volatile("cp.async.cg.shared.global [%0], [%1], 16;" :: "r"(d), "l"(s));
}
static __device__ __forceinline__ void ldsm4(uint32_t r[4], uint32_t addr){
    asm volatile("ldmatrix.sync.aligned.m8n8.x4.shared.b16 {%0,%1,%2,%3}, [%4];"
                 : "=r"(r[0]), "=r"(r[1]), "=r"(r[2]), "=r"(r[3]) : "r"(addr));
}
static __device__ __forceinline__ void mma16816(float c[4], const uint32_t a[4],
                                                uint32_t b0, uint32_t b1){
    asm volatile("mma.sync.aligned.m16n8k16.row.col.f32.bf16.bf16.f32 "
                 "{%0,%1,%2,%3}, {%4,%5,%6,%7}, {%8,%9}, {%0,%1,%2,%3};"
                 : "+f"(c[0]), "+f"(c[1]), "+f"(c[2]), "+f"(c[3])
                 : "r"(a[0]), "r"(a[1]), "r"(a[2]), "r"(a[3]), "r"(b0), "r"(b1));
}
static __device__ __forceinline__ uint32_t swz64(int row, int ch){
    return (uint32_t)row*64 + (uint32_t)(((ch + (row>>1)) & 3) << 4);
}
static __device__ __forceinline__ void split4(float4 v, uint2& hh, uint2& ll){
    __nv_bfloat162 h0 = __floats2bfloat162_rn(v.x, v.y);
    __nv_bfloat162 h1 = __floats2bfloat162_rn(v.z, v.w);
    float r0 = v.x - __bfloat162float(h0.x);
    float r1 = v.y - __bfloat162float(h0.y);
    float r2 = v.z - __bfloat162float(h1.x);
    float r3 = v.w - __bfloat162float(h1.y);
    __nv_bfloat162 l0 = __floats2bfloat162_rn(r0, r1);
    __nv_bfloat162 l1 = __floats2bfloat162_rn(r2, r3);
    hh.x = *reinterpret_cast<uint32_t*>(&h0);
    hh.y = *reinterpret_cast<uint32_t*>(&h1);
    ll.x = *reinterpret_cast<uint32_t*>(&l0);
    ll.y = *reinterpret_cast<uint32_t*>(&l1);
}
static __device__ __forceinline__ float gate_corr(const float* W_ih,
                                                  const float* fe, int row){
    const float* wr = W_ih + row*C_;
    float s = 0.f;
    #pragma unroll
    for (int k=0;k<C_;k++) s = fmaf(wr[k], fe[k], s);
    return s;
}

// ---------------------------------------------------------------------------
// mega_pre: [0,4096) split+zero | [4096,4416) conv | [4416,5056) gates
// ---------------------------------------------------------------------------
__global__ __launch_bounds__(256) void mega_pre_kernel(
    const float* __restrict__ W, const float* __restrict__ enc,
    const float* __restrict__ ap, const float* __restrict__ cw,
    const float* __restrict__ dec_z, const float* __restrict__ att_h,
    const float* __restrict__ W_dec, const float* __restrict__ W_hh,
    float* __restrict__ out)
{
    __shared__ float sm[2048];
    __shared__ float sm2[1024];
    __shared__ float red[256];
    const int bx = blockIdx.x, tid = threadIdx.x;

    if (bx < NB_SPLIT){
        const int n4e = B_*T_*E_/4;
        const int n4w = A_*E_/4;
        const int stride = NB_SPLIT*256;
        for (int i = bx*256 + tid; i < n4e; i += stride){
            uint2 hh, ll;
            split4(((const float4*)enc)[i], hh, ll);
            ((uint2*)g_eh)[i] = hh;
            ((uint2*)g_el)[i] = ll;
            if (i < n4w){
                split4(((const float4*)W)[i], hh, ll);
                ((uint2*)g_wh)[i] = hh;
                ((uint2*)g_wl)[i] = ll;
            }
            if (i < B_*T_) g_e[i] = 0.f;
            if (i < B_*E_) out[OUT_CTX + i] = 0.f;
        }
    } else if (bx < NB_SPLIT + NB_CONV){
        float* xp = sm;
        float* wk = sm2;
        int idx = bx - NB_SPLIT;
        int b = idx / C_, c = idx % C_;
        for (int i=tid;i<1816;i+=256){
            int t = i - FILTR;
            xp[i] = (t>=0 && t<T_) ? ap[b*T_+t] : 0.f;
        }
        for (int i=tid;i<KW+7;i+=256) wk[i] = (i<KW) ? cw[c*KW + i] : 0.f;
        __syncthreads();
        float m = 0.f;
        if (tid < 200){
            int t0 = tid*8;
            float x0=xp[t0],x1=xp[t0+1],x2=xp[t0+2],x3=xp[t0+3];
            float x4=xp[t0+4],x5=xp[t0+5],x6=xp[t0+6],x7=xp[t0+7];
            float a0=0.f,a1=0.f,a2=0.f,a3=0.f,a4=0.f,a5=0.f,a6=0.f,a7=0.f;
            #pragma unroll 4
            for (int k=0;k<KW;k++){
                float w = wk[k];
                a0 = fmaf(x0,w,a0); a1 = fmaf(x1,w,a1);
                a2 = fmaf(x2,w,a2); a3 = fmaf(x3,w,a3);
                a4 = fmaf(x4,w,a4); a5 = fmaf(x5,w,a5);
                a6 = fmaf(x6,w,a6); a7 = fmaf(x7,w,a7);
                x0=x1; x1=x2; x2=x3; x3=x4; x4=x5; x5=x6; x6=x7;
                x7 = xp[t0+k+8];
            }
            m = fmaxf(fmaxf(fmaxf(a0,a1),fmaxf(a2,a3)), fmaxf(fmaxf(a4,a5),fmaxf(a6,a7)));
        }
        red[tid]=m; __syncthreads();
        for (int s=128;s>0;s>>=1){ if (tid<s) red[tid]=fmaxf(red[tid],red[tid+s]); __syncthreads(); }
        if (tid==0) g_feat[b*C_+c] = red[0];
    } else {
        float* s_h = sm;
        float* s_z = sm + 512;
        int idx = bx - NB_SPLIT - NB_CONV;
        int b = idx / 20, j = idx % 20;
        int lane = tid & 31, wp = tid >> 5;
        s_h[tid]     = att_h[b*A_+tid];
        s_h[tid+256] = att_h[b*A_+tid+256];
        s_z[tid]     = dec_z[b*D_+tid];
        s_z[tid+256] = dec_z[b*D_+tid+256];
        s_z[tid+512] = dec_z[b*D_+tid+512];
        s_z[tid+768] = dec_z[b*D_+tid+768];
        __syncthreads();
        int rbase = j*128 + wp*16;
        #pragma unroll 1
        for (int i=0;i<16;i++){
            int r = rbase + i;
            float acc = 0.f;
            if (r < 4*A_){
                const float* wr = &W_hh[(size_t)r*A_];
                #pragma unroll
                for (int k=0;k<16;k++) acc = fmaf(wr[lane+32*k], s_h[lane+32*k], acc);
                #pragma unroll
                for (int o=16;o>0;o>>=1) acc += __shfl_xor_sync(0xffffffffu, acc, o);
                if (lane==0) g_gates[b*4*A_ + r] = acc;
            } else {
                int rd = r - 4*A_;
                const float* wr = &W_dec[(size_t)rd*D_];
                #pragma unroll
                for (int k=0;k<32;k++) acc = fmaf(wr[lane+32*k], s_z[lane+32*k], acc);
                #pragma unroll
                for (int o=16;o>0;o>>=1) acc += __shfl_xor_sync(0xffffffffu, acc, o);
                if (lane==0) g_dp[b*A_ + rd] = acc;
            }
        }
    }
}

// ---------------------------------------------------------------------------
// HMMA score kernel. CTA 128x256, 8 warps (2m x 4n), warp tile 64x64.
// KC=32, 3-stage, 1 CTA/SM, one barrier/kt, strength-reduced addressing.
// grid (2, 13, 32), a0 fastest (A-tile sharers adjacent).
// ---------------------------------------------------------------------------
__global__ void __launch_bounds__(256) score_kernel(
    const float* __restrict__ Wg,
    const float* __restrict__ att_c, const float* __restrict__ b_enc,
    const float* __restrict__ W_ih)
{
    extern __shared__ char smemc[];
    __shared__ float s_sv[NT];
    __shared__ float s_wg[NT];
    const uint32_t sb0 = smem_u32(smemc);
    const int tid = threadIdx.x;
    const int lane = tid & 31, wid = tid >> 5;
    const int warp_m = wid >> 2, warp_n = wid & 3;
    const int b  = blockIdx.z;
    const int t0 = blockIdx.y * MT;
    const int a0 = blockIdx.x * NT;

    {
        int a = a0 + tid;
        float fe[C_];
        #pragma unroll
        for (int k=0;k<C_;k++) fe[k] = g_feat[b*C_+k];
        float ig = g_gates[b*4*A_ + a]        + gate_corr(W_ih, fe, a);
        float fg = g_gates[b*4*A_ + A_ + a]   + gate_corr(W_ih, fe, A_ + a);
        float gg = g_gates[b*4*A_ + 2*A_ + a] + gate_corr(W_ih, fe, 2*A_ + a);
        float og = g_gates[b*4*A_ + 3*A_ + a] + gate_corr(W_ih, fe, 3*A_ + a);
        float cn = sigmf(fg)*att_c[b*A_+a] + sigmf(ig)*tanhf(gg);
        float hn = sigmf(og)*tanhf(cn);
        s_sv[tid] = g_dp[b*A_+a] + hn + b_enc[a];
        s_wg[tid] = Wg[a];
    }

    // cp.async setup: A 2 chunks/thread/array, B 4 chunks/thread/array
    uint32_t cpoA[2], cpoB[4];
    const char *pA_h[2], *pA_l[2], *pB_h[4], *pB_l[4];
    #pragma unroll
    for (int j=0;j<2;j++){
        int idx = j*256 + tid;
        int row = idx >> 2, ch = idx & 3;
        cpoA[j] = swz64(row, ch);
        size_t so = (size_t)row*E_ + ch*8;
        pA_h[j] = (const char*)(g_eh + (size_t)(b*T_ + t0)*E_ + so);
        pA_l[j] = (const char*)(g_el + (size_t)(b*T_ + t0)*E_ + so);
    }
    #pragma unroll
    for (int j=0;j<4;j++){
        int idx = j*256 + tid;
        int row = idx >> 2, ch = idx & 3;
        cpoB[j] = swz64(row, ch);
        size_t so = (size_t)row*E_ + ch*8;
        pB_h[j] = (const char*)(g_wh + (size_t)a0*E_ + so);
        pB_l[j] = (const char*)(g_wl + (size_t)a0*E_ + so);
    }
    uint32_t ld_st = 0;

    auto load_stage = [&](){
        #pragma unroll
        for (int j=0;j<2;j++){
            uint32_t d = sb0 + ld_st + cpoA[j];
            cp16(d,        pA_h[j]);
            cp16(d + 8192, pA_l[j]);
            pA_h[j] += 64; pA_l[j] += 64;
        }
        #pragma unroll
        for (int j=0;j<4;j++){
            uint32_t d = sb0 + ld_st + 16384 + cpoB[j];
            cp16(d,         pB_h[j]);
            cp16(d + 16384, pB_l[j]);
            pB_h[j] += 64; pB_l[j] += 64;
        }
        asm volatile("cp.async.commit_group;" ::: "memory");
        ld_st = (ld_st == 2*STAGE_B) ? 0u : ld_st + STAGE_B;
    };

    // ldsm offsets (kt-invariant): A rows warp_m*64 + mf*16 + lrow;
    // B rows warp_n*64 + g*16 + lrow
    const int lrow = lane & 15, lsel = lane >> 4;
    uint32_t ao[4][2], bo[4][2];
    #pragma unroll
    for (int k16=0;k16<2;k16++){
        int ch = k16*2 + lsel;
        #pragma unroll
        for (int mf=0; mf<4; mf++)
            ao[mf][k16] = swz64(warp_m*64 + mf*16 + lrow, ch);
        #pragma unroll
        for (int g=0; g<4; g++)
            bo[g][k16] = swz64(warp_n*64 + g*16 + lrow, ch);
    }

    float acc[4][8][4];
    #pragma unroll
    for (int i=0;i<4;i++)
        #pragma unroll
        for (int j=0;j<8;j++)
            #pragma unroll
            for (int k=0;k<4;k++) acc[i][j][k] = 0.f;

    load_stage();
    load_stage();

    uint32_t st = 0;
    #pragma unroll 1
    for (int kt = 0; kt < NKT; kt++){
        if (kt == NKT-1) asm volatile("cp.async.wait_group 0;" ::: "memory");
        else             asm volatile("cp.async.wait_group 1;" ::: "memory");
        __syncthreads();
        if (kt + 2 < NKT) load_stage();

        const uint32_t baseA = sb0 + st;
        const uint32_t baseBh = baseA + 16384;
        const uint32_t baseBl = baseA + 32768;
        st = (st == 2*STAGE_B) ? 0u : st + STAGE_B;
        #pragma unroll
        for (int k16=0; k16<2; k16++){
            // ---- Ah pass: Ah x (Bh, Bl) ----
            {
                uint32_t Ah[4][4];
                #pragma unroll
                for (int mf=0; mf<4; mf++) ldsm4(Ah[mf], baseA + ao[mf][k16]);
                #pragma unroll
                for (int g=0; g<4; g++){
                    uint32_t Bh[4], Bl[4];
                    ldsm4(Bh, baseBh + bo[g][k16]);
                    ldsm4(Bl, baseBl + bo[g][k16]);
                    #pragma unroll
                    for (int mf=0; mf<4; mf++){
                        mma16816(acc[mf][2*g],   Ah[mf], Bh[0], Bh[2]);
                        mma16816(acc[mf][2*g+1], Ah[mf], Bh[1], Bh[3]);
                        mma16816(acc[mf][2*g],   Ah[mf], Bl[0], Bl[2]);
                        mma16816(acc[mf][2*g+1], Ah[mf], Bl[1], Bl[3]);
                    }
                }
            }
            // ---- Al pass: Al x Bh ----
            {
                uint32_t Al[4][4];
                #pragma unroll
                for (int mf=0; mf<4; mf++) ldsm4(Al[mf], baseA + 8192 + ao[mf][k16]);
                #pragma unroll
                for (int g=0; g<4; g++){
                    uint32_t Bh[4];
                    ldsm4(Bh, baseBh + bo[g][k16]);
                    #pragma unroll
                    for (int mf=0; mf<4; mf++){
                        mma16816(acc[mf][2*g],   Al[mf], Bh[0], Bh[2]);
                        mma16816(acc[mf][2*g+1], Al[mf], Bh[1], Bh[3]);
                    }
                }
            }
        }
    }

    const int qh = lane >> 2, qr = lane & 3;
    #pragma unroll
    for (int mf=0; mf<4; mf++){
        float p0 = 0.f, p1 = 0.f;
        #pragma unroll
        for (int nf=0; nf<8; nf++){
            int a = warp_n*64 + nf*8 + 2*qr;
            const float* c = acc[mf][nf];
            p0 = fmaf(s_wg[a],   tanhf(c[0] + s_sv[a]),   p0);
            p0 = fmaf(s_wg[a+1], tanhf(c[1] + s_sv[a+1]), p0);
            p1 = fmaf(s_wg[a],   tanhf(c[2] + s_sv[a]),   p1);
            p1 = fmaf(s_wg[a+1], tanhf(c[3] + s_sv[a+1]), p1);
        }
        p0 += __shfl_xor_sync(0xffffffffu, p0, 1);
        p0 += __shfl_xor_sync(0xffffffffu, p0, 2);
        p1 += __shfl_xor_sync(0xffffffffu, p1, 1);
        p1 += __shfl_xor_sync(0xffffffffu, p1, 2);
        if (qr == 0){
            int t = t0 + warp_m*64 + mf*16 + qh;
            if (t < T_)     atomicAdd(&g_e[b*T_ + t],     p0);
            if (t+8 < T_)   atomicAdd(&g_e[b*T_ + t + 8], p1);
        }
    }
}

// ---------------------------------------------------------------------------
// masked scaled softmax + LSTM h/c outputs (fused)
// ---------------------------------------------------------------------------
__global__ void softmax_kernel(const int* __restrict__ len,
                               const float* __restrict__ att_c,
                               const float* __restrict__ W_ih,
                               float* __restrict__ out){
    __shared__ float se[T_];
    __shared__ float red[256];
    int b = blockIdx.x, tid = threadIdx.x;
    int L = len[b];
    for (int t=tid;t<T_;t+=256) se[t] = g_e[b*T_+t];
    {
        float fe[C_];
        #pragma unroll
        for (int k=0;k<C_;k++) fe[k] = g_feat[b*C_+k];
        #pragma unroll
        for (int p=0;p<2;p++){
            int a = p*256 + tid;
            float ig = g_gates[b*4*A_ + a]        + gate_corr(W_ih, fe, a);
            float fg = g_gates[b*4*A_ + A_ + a]   + gate_corr(W_ih, fe, A_ + a);
            float gg = g_gates[b*4*A_ + 2*A_ + a] + gate_corr(W_ih, fe, 2*A_ + a);
            float og = g_gates[b*4*A_ + 3*A_ + a] + gate_corr(W_ih, fe, 3*A_ + a);
            float cn = sigmf(fg)*att_c[b*A_+a] + sigmf(ig)*tanhf(gg);
            float hn = sigmf(og)*tanhf(cn);
            out[OUT_H  + b*A_ + a] = hn;
            out[OUT_CN + b*A_ + a] = cn;
        }
    }
    __syncthreads();
    float m = -3.4e38f;
    for (int t=tid;t<L;t+=256) m = fmaxf(m, se[t]);
    red[tid]=m; __syncthreads();
    for (int s=128;s>0;s>>=1){ if (tid<s) red[tid]=fmaxf(red[tid],red[tid+s]); __syncthreads(); }
    m = red[0];
    __syncthreads();
    float sum = 0.f;
    for (int t=tid;t<T_;t+=256){
        float v = (t<L) ? expf(2.0f*(se[t]-m)) : 0.f;
        se[t] = v;
        sum += v;
    }
    red[tid]=sum; __syncthreads();
    for (int s=128;s>0;s>>=1){ if (tid<s) red[tid]+=red[tid+s]; __syncthreads(); }
    float inv = 1.0f/red[0];
    for (int t=tid;t<T_;t+=256) out[OUT_W + b*T_ + t] = se[t]*inv;
}

// ---------------------------------------------------------------------------
// ctx = w @ enc, split over t (8 ways), atomic accumulation
// ---------------------------------------------------------------------------
__global__ void ctx_kernel(const float* __restrict__ enc, float* __restrict__ out){
    __shared__ float sw[200];
    int b = blockIdx.x;
    int ec = blockIdx.y*256 + threadIdx.x;
    int tbase = blockIdx.z * 200;
    if (threadIdx.x < 200) sw[threadIdx.x] = out[OUT_W + b*T_ + tbase + threadIdx.x];
    __syncthreads();
    const float* eb = enc + ((size_t)b*T_ + tbase)*E_ + ec;
    float a0=0.f,a1=0.f,a2=0.f,a3=0.f,a4=0.f,a5=0.f,a6=0.f,a7=0.f;
    #pragma unroll 1
    for (int t=0;t<200;t+=8){
        a0 = fmaf(sw[t+0], eb[(size_t)(t+0)*E_], a0);
        a1 = fmaf(sw[t+1], eb[(size_t)(t+1)*E_], a1);
        a2 = fmaf(sw[t+2], eb[(size_t)(t+2)*E_], a2);
        a3 = fmaf(sw[t+3], eb[(size_t)(t+3)*E_], a3);
        a4 = fmaf(sw[t+4], eb[(size_t)(t+4)*E_], a4);
        a5 = fmaf(sw[t+5], eb[(size_t)(t+5)*E_], a5);
        a6 = fmaf(sw[t+6], eb[(size_t)(t+6)*E_], a6);
        a7 = fmaf(sw[t+7], eb[(size_t)(t+7)*E_], a7);
    }
    atomicAdd(&out[OUT_CTX + b*E_ + ec], ((a0+a1)+(a2+a3)) + ((a4+a5)+(a6+a7)));
}

// ---------------------------------------------------------------------------
extern "C" void kernel_launch(void* const* d_in, const int* in_sizes, int n_in,
                              void* d_out, int out_size)
{
    const float* enc      = (const float*)d_in[0];
    const int*   len      = (const int*)  d_in[1];
    const float* dec_z    = (const float*)d_in[2];
    const float* att_prev = (const float*)d_in[3];
    const float* att_h    = (const float*)d_in[4];
    const float* att_c    = (const float*)d_in[5];
    const float* W_enc    = (const float*)d_in[6];
    const float* b_enc    = (const float*)d_in[7];
    const float* W_dec    = (const float*)d_in[8];
    const float* conv_w   = (const float*)d_in[9];
    const float* W_ih     = (const float*)d_in[10];
    const float* W_hh     = (const float*)d_in[11];
    const float* W_g      = (const float*)d_in[12];
    float* out = (float*)d_out;

    cudaFuncSetAttribute(score_kernel,
                         cudaFuncAttributeMaxDynamicSharedMemorySize, SMEM_DYN);

    mega_pre_kernel<<<NB_SPLIT + NB_CONV + NB_GATES, 256>>>(
        W_enc, enc, att_prev, conv_w, dec_z, att_h, W_dec, W_hh, out);
    score_kernel<<<dim3(A_/NT, MTILES, B_), 256, SMEM_DYN>>>(W_g, att_c, b_enc, W_ih);
    softmax_kernel<<<B_, 256>>>(len, att_c, W_ih, out);
    ctx_kernel<<<dim3(B_, E_/256, 8), 256>>>(enc, out);
}

// round 14
// speedup vs baseline: 1.1852x; 1.1852x over previous
#include <cuda_runtime.h>
#include <cuda_bf16.h>
#include <cstdint>
#include <math.h>

#define B_   32
#define T_   1600
#define E_   1024
#define D_   1024
#define A_   512
#define C_   10
#define KW   201
#define FILTR 100

// output layout: ctx (B,E), w (B,T), h_new (B,A), c_new (B,A)
#define OUT_CTX 0
#define OUT_W   (B_*E_)
#define OUT_H   (OUT_W + B_*T_)
#define OUT_CN  (OUT_H + B_*A_)

// GEMM tiling
#define MT   128
#define NT   128
#define KC   32
#define NKT  (E_/KC)              // 32
#define MTILES ((T_ + MT - 1)/MT) // 13

// dynamic smem: 3 stages x 32KB (Ah/Al/Bh/Bl 8KB each)
#define STAGE_B 32768u
#define SMEM_DYN 98304

// mega_pre block ranges
#define NB_SPLIT 4096
#define NB_CONV  (B_*C_)          // 320
#define NB_GATES 640

// -------- scratch --------
__device__ __nv_bfloat16 g_eh[(size_t)(B_*T_ + MT) * E_];
__device__ __nv_bfloat16 g_el[(size_t)(B_*T_ + MT) * E_];
__device__ __nv_bfloat16 g_wh[(size_t)A_ * E_];
__device__ __nv_bfloat16 g_wl[(size_t)A_ * E_];
__device__ float g_feat[B_*C_];
__device__ float g_gates[B_*4*A_];   // W_hh@h part only (W_ih@feat added later)
__device__ float g_dp[B_*A_];
__device__ float g_e[B_*T_];

static __device__ __forceinline__ float sigmf(float x){ return 1.0f/(1.0f+expf(-x)); }
static __device__ __forceinline__ unsigned smem_u32(const void* p){
    return (unsigned)__cvta_generic_to_shared(p);
}
static __device__ __forceinline__ void cp16(unsigned d, const void* s){
    asm volatile("cp.async.cg.shared.global [%0], [%1], 16;" :: "r"(d), "l"(s));
}
static __device__ __forceinline__ void ldsm4(uint32_t r[4], uint32_t addr){
    asm volatile("ldmatrix.sync.aligned.m8n8.x4.shared.b16 {%0,%1,%2,%3}, [%4];"
                 : "=r"(r[0]), "=r"(r[1]), "=r"(r[2]), "=r"(r[3]) : "r"(addr));
}
static __device__ __forceinline__ void mma16816(float c[4], const uint32_t a[4],
                                                uint32_t b0, uint32_t b1){
    asm volatile("mma.sync.aligned.m16n8k16.row.col.f32.bf16.bf16.f32 "
                 "{%0,%1,%2,%3}, {%4,%5,%6,%7}, {%8,%9}, {%0,%1,%2,%3};"
                 : "+f"(c[0]), "+f"(c[1]), "+f"(c[2]), "+f"(c[3])
                 : "r"(a[0]), "r"(a[1]), "r"(a[2]), "r"(a[3]), "r"(b0), "r"(b1));
}
static __device__ __forceinline__ uint32_t swz64(int row, int ch){
    return (uint32_t)row*64 + (uint32_t)(((ch + (row>>1)) & 3) << 4);
}
static __device__ __forceinline__ void split4(float4 v, uint2& hh, uint2& ll){
    __nv_bfloat162 h0 = __floats2bfloat162_rn(v.x, v.y);
    __nv_bfloat162 h1 = __floats2bfloat162_rn(v.z, v.w);
    float r0 = v.x - __bfloat162float(h0.x);
    float r1 = v.y - __bfloat162float(h0.y);
    float r2 = v.z - __bfloat162float(h1.x);
    float r3 = v.w - __bfloat162float(h1.y);
    __nv_bfloat162 l0 = __floats2bfloat162_rn(r0, r1);
    __nv_bfloat162 l1 = __floats2bfloat162_rn(r2, r3);
    hh.x = *reinterpret_cast<uint32_t*>(&h0);
    hh.y = *reinterpret_cast<uint32_t*>(&h1);
    ll.x = *reinterpret_cast<uint32_t*>(&l0);
    ll.y = *reinterpret_cast<uint32_t*>(&l1);
}
static __device__ __forceinline__ float gate_corr(const float* W_ih,
                                                  const float* fe, int row){
    const float* wr = W_ih + row*C_;
    float s = 0.f;
    #pragma unroll
    for (int k=0;k<C_;k++) s = fmaf(wr[k], fe[k], s);
    return s;
}
static __device__ __forceinline__ float4 ldcs4(const float4* p){
    float4 v;
    asm("ld.global.cs.v4.f32 {%0,%1,%2,%3}, [%4];"
        : "=f"(v.x), "=f"(v.y), "=f"(v.z), "=f"(v.w) : "l"(p));
    return v;
}

// ---------------------------------------------------------------------------
// mega_pre: [0,4096) enc/W split + zeroing | [4096,4416) conv | [4416,5056) gates
// ---------------------------------------------------------------------------
__global__ __launch_bounds__(256) void mega_pre_kernel(
    const float* __restrict__ W, const float* __restrict__ enc,
    const float* __restrict__ ap, const float* __restrict__ cw,
    const float* __restrict__ dec_z, const float* __restrict__ att_h,
    const float* __restrict__ W_dec, const float* __restrict__ W_hh,
    float* __restrict__ out)
{
    __shared__ float sm[2048];
    __shared__ float sm2[1024];
    __shared__ float red[256];
    const int bx = blockIdx.x, tid = threadIdx.x;

    if (bx < NB_SPLIT){
        const int n4e = B_*T_*E_/4;
        const int n4w = A_*E_/4;
        const int stride = NB_SPLIT*256;
        for (int i = bx*256 + tid; i < n4e; i += stride){
            uint2 hh, ll;
            split4(ldcs4((const float4*)enc + i), hh, ll);
            ((uint2*)g_eh)[i] = hh;
            ((uint2*)g_el)[i] = ll;
            if (i < n4w){
                split4(((const float4*)W)[i], hh, ll);
                ((uint2*)g_wh)[i] = hh;
                ((uint2*)g_wl)[i] = ll;
            }
            if (i < B_*T_) g_e[i] = 0.f;
            if (i < B_*E_) out[OUT_CTX + i] = 0.f;
        }
    } else if (bx < NB_SPLIT + NB_CONV){
        float* xp = sm;
        float* wk = sm2;
        int idx = bx - NB_SPLIT;
        int b = idx / C_, c = idx % C_;
        for (int i=tid;i<1816;i+=256){
            int t = i - FILTR;
            xp[i] = (t>=0 && t<T_) ? ap[b*T_+t] : 0.f;
        }
        for (int i=tid;i<KW+7;i+=256) wk[i] = (i<KW) ? cw[c*KW + i] : 0.f;
        __syncthreads();
        float m = 0.f;
        if (tid < 200){
            int t0 = tid*8;
            float x0=xp[t0],x1=xp[t0+1],x2=xp[t0+2],x3=xp[t0+3];
            float x4=xp[t0+4],x5=xp[t0+5],x6=xp[t0+6],x7=xp[t0+7];
            float a0=0.f,a1=0.f,a2=0.f,a3=0.f,a4=0.f,a5=0.f,a6=0.f,a7=0.f;
            #pragma unroll 4
            for (int k=0;k<KW;k++){
                float w = wk[k];
                a0 = fmaf(x0,w,a0); a1 = fmaf(x1,w,a1);
                a2 = fmaf(x2,w,a2); a3 = fmaf(x3,w,a3);
                a4 = fmaf(x4,w,a4); a5 = fmaf(x5,w,a5);
                a6 = fmaf(x6,w,a6); a7 = fmaf(x7,w,a7);
                x0=x1; x1=x2; x2=x3; x3=x4; x4=x5; x5=x6; x6=x7;
                x7 = xp[t0+k+8];
            }
            m = fmaxf(fmaxf(fmaxf(a0,a1),fmaxf(a2,a3)), fmaxf(fmaxf(a4,a5),fmaxf(a6,a7)));
        }
        red[tid]=m; __syncthreads();
        for (int s=128;s>0;s>>=1){ if (tid<s) red[tid]=fmaxf(red[tid],red[tid+s]); __syncthreads(); }
        if (tid==0) g_feat[b*C_+c] = red[0];
    } else {
        float* s_h = sm;
        float* s_z = sm + 512;
        int idx = bx - NB_SPLIT - NB_CONV;
        int b = idx / 20, j = idx % 20;
        int lane = tid & 31, wp = tid >> 5;
        s_h[tid]     = att_h[b*A_+tid];
        s_h[tid+256] = att_h[b*A_+tid+256];
        s_z[tid]     = dec_z[b*D_+tid];
        s_z[tid+256] = dec_z[b*D_+tid+256];
        s_z[tid+512] = dec_z[b*D_+tid+512];
        s_z[tid+768] = dec_z[b*D_+tid+768];
        __syncthreads();
        int rbase = j*128 + wp*16;
        #pragma unroll 1
        for (int i=0;i<16;i++){
            int r = rbase + i;
            float acc = 0.f;
            if (r < 4*A_){
                const float* wr = &W_hh[(size_t)r*A_];
                #pragma unroll
                for (int k=0;k<16;k++) acc = fmaf(wr[lane+32*k], s_h[lane+32*k], acc);
                #pragma unroll
                for (int o=16;o>0;o>>=1) acc += __shfl_xor_sync(0xffffffffu, acc, o);
                if (lane==0) g_gates[b*4*A_ + r] = acc;
            } else {
                int rd = r - 4*A_;
                const float* wr = &W_dec[(size_t)rd*D_];
                #pragma unroll
                for (int k=0;k<32;k++) acc = fmaf(wr[lane+32*k], s_z[lane+32*k], acc);
                #pragma unroll
                for (int o=16;o>0;o>>=1) acc += __shfl_xor_sync(0xffffffffu, acc, o);
                if (lane==0) g_dp[b*A_ + rd] = acc;
            }
        }
    }
}

// ---------------------------------------------------------------------------
// HMMA score kernel (R12 config). 256 threads = 8 warps (4m x 2n), warp tile
// 32x64. KC=32, 3-stage, 2 CTAs/SM, one barrier/kt, strength-reduced.
// ---------------------------------------------------------------------------
__global__ void __launch_bounds__(256, 2) score_kernel(
    const float* __restrict__ Wg,
    const float* __restrict__ att_c, const float* __restrict__ b_enc,
    const float* __restrict__ W_ih)
{
    extern __shared__ char smemc[];
    __shared__ float s_sv[NT];
    __shared__ float s_wg[NT];
    const uint32_t sb0 = smem_u32(smemc);
    const int tid = threadIdx.x;
    const int lane = tid & 31, wid = tid >> 5;
    const int warp_m = wid >> 1, warp_n = wid & 1;
    const int b  = blockIdx.z;
    const int t0 = blockIdx.y * MT;
    const int a0 = blockIdx.x * NT;

    if (tid < NT){
        int a = a0 + tid;
        float fe[C_];
        #pragma unroll
        for (int k=0;k<C_;k++) fe[k] = g_feat[b*C_+k];
        float ig = g_gates[b*4*A_ + a]        + gate_corr(W_ih, fe, a);
        float fg = g_gates[b*4*A_ + A_ + a]   + gate_corr(W_ih, fe, A_ + a);
        float gg = g_gates[b*4*A_ + 2*A_ + a] + gate_corr(W_ih, fe, 2*A_ + a);
        float og = g_gates[b*4*A_ + 3*A_ + a] + gate_corr(W_ih, fe, 3*A_ + a);
        float cn = sigmf(fg)*att_c[b*A_+a] + sigmf(ig)*tanhf(gg);
        float hn = sigmf(og)*tanhf(cn);
        s_sv[tid] = g_dp[b*A_+a] + hn + b_enc[a];
        s_wg[tid] = Wg[a];
    }

    uint32_t cpo[2];
    const char *pA_h[2], *pA_l[2], *pB_h[2], *pB_l[2];
    #pragma unroll
    for (int j=0;j<2;j++){
        int idx = j*256 + tid;
        int row = idx >> 2, ch = idx & 3;
        cpo[j] = swz64(row, ch);
        size_t so = (size_t)row*E_ + ch*8;
        pA_h[j] = (const char*)(g_eh + (size_t)(b*T_ + t0)*E_ + so);
        pA_l[j] = (const char*)(g_el + (size_t)(b*T_ + t0)*E_ + so);
        pB_h[j] = (const char*)(g_wh + (size_t)a0*E_ + so);
        pB_l[j] = (const char*)(g_wl + (size_t)a0*E_ + so);
    }
    uint32_t ld_st = 0;

    auto load_stage = [&](){
        #pragma unroll
        for (int j=0;j<2;j++){
            uint32_t d = sb0 + ld_st + cpo[j];
            cp16(d,          pA_h[j]);
            cp16(d + 8192,   pA_l[j]);
            cp16(d + 16384,  pB_h[j]);
            cp16(d + 24576,  pB_l[j]);
            pA_h[j] += 64; pA_l[j] += 64; pB_h[j] += 64; pB_l[j] += 64;
        }
        asm volatile("cp.async.commit_group;" ::: "memory");
        ld_st = (ld_st == 2*STAGE_B) ? 0u : ld_st + STAGE_B;
    };

    const int lrow = lane & 15, lsel = lane >> 4;
    const int arow0 = warp_m*32 + lrow, arow1 = arow0 + 16;
    uint32_t ao0[2], ao1[2], bo[4][2];
    #pragma unroll
    for (int k16=0;k16<2;k16++){
        int ch = k16*2 + lsel;
        ao0[k16] = swz64(arow0, ch);
        ao1[k16] = swz64(arow1, ch);
        #pragma unroll
        for (int g=0; g<4; g++)
            bo[g][k16] = swz64(warp_n*64 + g*16 + lrow, ch);
    }

    float acc[2][8][4];
    #pragma unroll
    for (int i=0;i<2;i++)
        #pragma unroll
        for (int j=0;j<8;j++)
            #pragma unroll
            for (int k=0;k<4;k++) acc[i][j][k] = 0.f;

    load_stage();
    load_stage();

    uint32_t st = 0;
    #pragma unroll 1
    for (int kt = 0; kt < NKT; kt++){
        if (kt == NKT-1) asm volatile("cp.async.wait_group 0;" ::: "memory");
        else             asm volatile("cp.async.wait_group 1;" ::: "memory");
        __syncthreads();
        if (kt + 2 < NKT) load_stage();

        const uint32_t base = sb0 + st;
        st = (st == 2*STAGE_B) ? 0u : st + STAGE_B;
        #pragma unroll
        for (int k16=0; k16<2; k16++){
            uint32_t Ah0[4], Ah1[4], Al0[4], Al1[4];
            ldsm4(Ah0, base + ao0[k16]);
            ldsm4(Ah1, base + ao1[k16]);
            ldsm4(Al0, base + 8192 + ao0[k16]);
            ldsm4(Al1, base + 8192 + ao1[k16]);
            #pragma unroll
            for (int g=0; g<4; g++){
                uint32_t Bh[4], Bl[4];
                ldsm4(Bh, base + 16384 + bo[g][k16]);
                ldsm4(Bl, base + 24576 + bo[g][k16]);
                mma16816(acc[0][2*g],   Ah0, Bh[0], Bh[2]);
                mma16816(acc[0][2*g+1], Ah0, Bh[1], Bh[3]);
                mma16816(acc[1][2*g],   Ah1, Bh[0], Bh[2]);
                mma16816(acc[1][2*g+1], Ah1, Bh[1], Bh[3]);
                mma16816(acc[0][2*g],   Ah0, Bl[0], Bl[2]);
                mma16816(acc[0][2*g+1], Ah0, Bl[1], Bl[3]);
                mma16816(acc[1][2*g],   Ah1, Bl[0], Bl[2]);
                mma16816(acc[1][2*g+1], Ah1, Bl[1], Bl[3]);
                mma16816(acc[0][2*g],   Al0, Bh[0], Bh[2]);
                mma16816(acc[0][2*g+1], Al0, Bh[1], Bh[3]);
                mma16816(acc[1][2*g],   Al1, Bh[0], Bh[2]);
                mma16816(acc[1][2*g+1], Al1, Bh[1], Bh[3]);
            }
        }
    }

    const int qh = lane >> 2, qr = lane & 3;
    #pragma unroll
    for (int mi=0; mi<2; mi++){
        float p0 = 0.f, p1 = 0.f;
        #pragma unroll
        for (int nf=0; nf<8; nf++){
            int a = warp_n*64 + nf*8 + 2*qr;
            const float* c = acc[mi][nf];
            p0 = fmaf(s_wg[a],   tanhf(c[0] + s_sv[a]),   p0);
            p0 = fmaf(s_wg[a+1], tanhf(c[1] + s_sv[a+1]), p0);
            p1 = fmaf(s_wg[a],   tanhf(c[2] + s_sv[a]),   p1);
            p1 = fmaf(s_wg[a+1], tanhf(c[3] + s_sv[a+1]), p1);
        }
        p0 += __shfl_xor_sync(0xffffffffu, p0, 1);
        p0 += __shfl_xor_sync(0xffffffffu, p0, 2);
        p1 += __shfl_xor_sync(0xffffffffu, p1, 1);
        p1 += __shfl_xor_sync(0xffffffffu, p1, 2);
        if (qr == 0){
            int t = t0 + warp_m*32 + mi*16 + qh;
            if (t < T_)     atomicAdd(&g_e[b*T_ + t],     p0);
            if (t+8 < T_)   atomicAdd(&g_e[b*T_ + t + 8], p1);
        }
    }
}

// ---------------------------------------------------------------------------
// masked scaled softmax + LSTM h/c outputs (fused)
// ---------------------------------------------------------------------------
__global__ void softmax_kernel(const int* __restrict__ len,
                               const float* __restrict__ att_c,
                               const float* __restrict__ W_ih,
                               float* __restrict__ out){
    __shared__ float se[T_];
    __shared__ float red[256];
    int b = blockIdx.x, tid = threadIdx.x;
    int L = len[b];
    for (int t=tid;t<T_;t+=256) se[t] = g_e[b*T_+t];
    {
        float fe[C_];
        #pragma unroll
        for (int k=0;k<C_;k++) fe[k] = g_feat[b*C_+k];
        #pragma unroll
        for (int p=0;p<2;p++){
            int a = p*256 + tid;
            float ig = g_gates[b*4*A_ + a]        + gate_corr(W_ih, fe, a);
            float fg = g_gates[b*4*A_ + A_ + a]   + gate_corr(W_ih, fe, A_ + a);
            float gg = g_gates[b*4*A_ + 2*A_ + a] + gate_corr(W_ih, fe, 2*A_ + a);
            float og = g_gates[b*4*A_ + 3*A_ + a] + gate_corr(W_ih, fe, 3*A_ + a);
            float cn = sigmf(fg)*att_c[b*A_+a] + sigmf(ig)*tanhf(gg);
            float hn = sigmf(og)*tanhf(cn);
            out[OUT_H  + b*A_ + a] = hn;
            out[OUT_CN + b*A_ + a] = cn;
        }
    }
    __syncthreads();
    float m = -3.4e38f;
    for (int t=tid;t<L;t+=256) m = fmaxf(m, se[t]);
    red[tid]=m; __syncthreads();
    for (int s=128;s>0;s>>=1){ if (tid<s) red[tid]=fmaxf(red[tid],red[tid+s]); __syncthreads(); }
    m = red[0];
    __syncthreads();
    float sum = 0.f;
    for (int t=tid;t<T_;t+=256){
        float v = (t<L) ? expf(2.0f*(se[t]-m)) : 0.f;
        se[t] = v;
        sum += v;
    }
    red[tid]=sum; __syncthreads();
    for (int s=128;s>0;s>>=1){ if (tid<s) red[tid]+=red[tid+s]; __syncthreads(); }
    float inv = 1.0f/red[0];
    for (int t=tid;t<T_;t+=256) out[OUT_W + b*T_ + t] = se[t]*inv;
}

// ---------------------------------------------------------------------------
// ctx = w @ enc, split over t (8 ways), atomic accumulation, streaming loads
// ---------------------------------------------------------------------------
__global__ void ctx_kernel(const float* __restrict__ enc, float* __restrict__ out){
    __shared__ float sw[200];
    int b = blockIdx.x;
    int ec = blockIdx.y*256 + threadIdx.x;
    int tbase = blockIdx.z * 200;
    if (threadIdx.x < 200) sw[threadIdx.x] = out[OUT_W + b*T_ + tbase + threadIdx.x];
    __syncthreads();
    const float* eb = enc + ((size_t)b*T_ + tbase)*E_ + ec;
    float a0=0.f,a1=0.f,a2=0.f,a3=0.f,a4=0.f,a5=0.f,a6=0.f,a7=0.f;
    #pragma unroll 1
    for (int t=0;t<200;t+=8){
        float e0 = __ldcs(&eb[(size_t)(t+0)*E_]);
        float e1 = __ldcs(&eb[(size_t)(t+1)*E_]);
        float e2 = __ldcs(&eb[(size_t)(t+2)*E_]);
        float e3 = __ldcs(&eb[(size_t)(t+3)*E_]);
        float e4 = __ldcs(&eb[(size_t)(t+4)*E_]);
        float e5 = __ldcs(&eb[(size_t)(t+5)*E_]);
        float e6 = __ldcs(&eb[(size_t)(t+6)*E_]);
        float e7 = __ldcs(&eb[(size_t)(t+7)*E_]);
        a0 = fmaf(sw[t+0], e0, a0);
        a1 = fmaf(sw[t+1], e1, a1);
        a2 = fmaf(sw[t+2], e2, a2);
        a3 = fmaf(sw[t+3], e3, a3);
        a4 = fmaf(sw[t+4], e4, a4);
        a5 = fmaf(sw[t+5], e5, a5);
        a6 = fmaf(sw[t+6], e6, a6);
        a7 = fmaf(sw[t+7], e7, a7);
    }
    atomicAdd(&out[OUT_CTX + b*E_ + ec], ((a0+a1)+(a2+a3)) + ((a4+a5)+(a6+a7)));
}

// ---------------------------------------------------------------------------
extern "C" void kernel_launch(void* const* d_in, const int* in_sizes, int n_in,
                              void* d_out, int out_size)
{
    const float* enc      = (const float*)d_in[0];
    const int*   len      = (const int*)  d_in[1];
    const float* dec_z    = (const float*)d_in[2];
    const float* att_prev = (const float*)d_in[3];
    const float* att_h    = (const float*)d_in[4];
    const float* att_c    = (const float*)d_in[5];
    const float* W_enc    = (const float*)d_in[6];
    const float* b_enc    = (const float*)d_in[7];
    const float* W_dec    = (const float*)d_in[8];
    const float* conv_w   = (const float*)d_in[9];
    const float* W_ih     = (const float*)d_in[10];
    const float* W_hh     = (const float*)d_in[11];
    const float* W_g      = (const float*)d_in[12];
    float* out = (float*)d_out;

    cudaFuncSetAttribute(score_kernel,
                         cudaFuncAttributeMaxDynamicSharedMemorySize, SMEM_DYN);

    mega_pre_kernel<<<NB_SPLIT + NB_CONV + NB_GATES, 256>>>(
        W_enc, enc, att_prev, conv_w, dec_z, att_h, W_dec, W_hh, out);
    score_kernel<<<dim3(A_/NT, MTILES, B_), 256, SMEM_DYN>>>(W_g, att_c, b_enc, W_ih);
    softmax_kernel<<<B_, 256>>>(len, att_c, W_ih, out);
    ctx_kernel<<<dim3(B_, E_/256, 8), 256>>>(enc, out);
}

// round 15
// speedup vs baseline: 1.4819x; 1.2503x over previous
#include <cuda_runtime.h>
#include <cuda_fp16.h>
#include <cstdint>
#include <math.h>

#define B_   32
#define T_   1600
#define E_   1024
#define D_   1024
#define A_   512
#define C_   10
#define KW   201
#define FILTR 100

// output layout: ctx (B,E), w (B,T), h_new (B,A), c_new (B,A)
#define OUT_CTX 0
#define OUT_W   (B_*E_)
#define OUT_H   (OUT_W + B_*T_)
#define OUT_CN  (OUT_H + B_*A_)

// GEMM tiling
#define MT   128
#define NT   128
#define KC   32
#define NKT  (E_/KC)              // 32
#define MTILES ((T_ + MT - 1)/MT) // 13

// dynamic smem: 3 stages x 24KB (Ah 8K | Al 8K | Bh 8K)
#define STAGE_B 24576u
#define SMEM_DYN 73728

// mega_pre block ranges
#define NB_SPLIT 4096
#define NB_CONV  (B_*C_)          // 320
#define NB_GATES 640

// -------- scratch --------
__device__ __half g_eh[(size_t)(B_*T_ + MT) * E_];   // enc fp16 hi (pad rows 0)
__device__ __half g_el[(size_t)(B_*T_ + MT) * E_];   // enc fp16 lo
__device__ __half g_wh[(size_t)A_ * E_];             // W_enc fp16 (hi only)
__device__ float g_feat[B_*C_];
__device__ float g_gates[B_*4*A_];   // W_hh@h part only (W_ih@feat added later)
__device__ float g_dp[B_*A_];
__device__ float g_e[B_*T_];

static __device__ __forceinline__ float sigmf(float x){ return 1.0f/(1.0f+expf(-x)); }
static __device__ __forceinline__ unsigned smem_u32(const void* p){
    return (unsigned)__cvta_generic_to_shared(p);
}
static __device__ __forceinline__ void cp16(unsigned d, const void* s){
    asm volatile("cp.async.cg.shared.global [%0], [%1], 16;" :: "r"(d), "l"(s));
}
static __device__ __forceinline__ void ldsm4(uint32_t r[4], uint32_t addr){
    asm volatile("ldmatrix.sync.aligned.m8n8.x4.shared.b16 {%0,%1,%2,%3}, [%4];"
                 : "=r"(r[0]), "=r"(r[1]), "=r"(r[2]), "=r"(r[3]) : "r"(addr));
}
static __device__ __forceinline__ void mma16816(float c[4], const uint32_t a[4],
                                                uint32_t b0, uint32_t b1){
    asm volatile("mma.sync.aligned.m16n8k16.row.col.f32.f16.f16.f32 "
                 "{%0,%1,%2,%3}, {%4,%5,%6,%7}, {%8,%9}, {%0,%1,%2,%3};"
                 : "+f"(c[0]), "+f"(c[1]), "+f"(c[2]), "+f"(c[3])
                 : "r"(a[0]), "r"(a[1]), "r"(a[2]), "r"(a[3]), "r"(b0), "r"(b1));
}
static __device__ __forceinline__ uint32_t swz64(int row, int ch){
    return (uint32_t)row*64 + (uint32_t)(((ch + (row>>1)) & 3) << 4);
}
// fp16 hi/lo split of 4 floats
static __device__ __forceinline__ void split4h(float4 v, uint2& hh, uint2& ll){
    __half h0 = __float2half_rn(v.x);
    __half h1 = __float2half_rn(v.y);
    __half h2 = __float2half_rn(v.z);
    __half h3 = __float2half_rn(v.w);
    __half l0 = __float2half_rn(v.x - __half2float(h0));
    __half l1 = __float2half_rn(v.y - __half2float(h1));
    __half l2 = __float2half_rn(v.z - __half2float(h2));
    __half l3 = __float2half_rn(v.w - __half2float(h3));
    __half2 hp0 = __halves2half2(h0, h1), hp1 = __halves2half2(h2, h3);
    __half2 lp0 = __halves2half2(l0, l1), lp1 = __halves2half2(l2, l3);
    hh.x = *reinterpret_cast<uint32_t*>(&hp0);
    hh.y = *reinterpret_cast<uint32_t*>(&hp1);
    ll.x = *reinterpret_cast<uint32_t*>(&lp0);
    ll.y = *reinterpret_cast<uint32_t*>(&lp1);
}
static __device__ __forceinline__ uint2 round4h(float4 v){
    __half2 p0 = __floats2half2_rn(v.x, v.y);
    __half2 p1 = __floats2half2_rn(v.z, v.w);
    uint2 r;
    r.x = *reinterpret_cast<uint32_t*>(&p0);
    r.y = *reinterpret_cast<uint32_t*>(&p1);
    return r;
}
static __device__ __forceinline__ float gate_corr(const float* W_ih,
                                                  const float* fe, int row){
    const float* wr = W_ih + row*C_;
    float s = 0.f;
    #pragma unroll
    for (int k=0;k<C_;k++) s = fmaf(wr[k], fe[k], s);
    return s;
}
static __device__ __forceinline__ float4 ldcs4(const float4* p){
    float4 v;
    asm("ld.global.cs.v4.f32 {%0,%1,%2,%3}, [%4];"
        : "=f"(v.x), "=f"(v.y), "=f"(v.z), "=f"(v.w) : "l"(p));
    return v;
}

// ---------------------------------------------------------------------------
// mega_pre: [0,4096) enc/W split + zeroing | [4096,4416) conv | [4416,5056) gates
// ---------------------------------------------------------------------------
__global__ __launch_bounds__(256) void mega_pre_kernel(
    const float* __restrict__ W, const float* __restrict__ enc,
    const float* __restrict__ ap, const float* __restrict__ cw,
    const float* __restrict__ dec_z, const float* __restrict__ att_h,
    const float* __restrict__ W_dec, const float* __restrict__ W_hh,
    float* __restrict__ out)
{
    __shared__ float sm[2048];
    __shared__ float sm2[1024];
    __shared__ float red[256];
    const int bx = blockIdx.x, tid = threadIdx.x;

    if (bx < NB_SPLIT){
        const int n4e = B_*T_*E_/4;
        const int n4w = A_*E_/4;
        const int stride = NB_SPLIT*256;
        for (int i = bx*256 + tid; i < n4e; i += stride){
            uint2 hh, ll;
            split4h(ldcs4((const float4*)enc + i), hh, ll);
            ((uint2*)g_eh)[i] = hh;
            ((uint2*)g_el)[i] = ll;
            if (i < n4w){
                ((uint2*)g_wh)[i] = round4h(((const float4*)W)[i]);
            }
            if (i < B_*T_) g_e[i] = 0.f;
            if (i < B_*E_) out[OUT_CTX + i] = 0.f;
        }
    } else if (bx < NB_SPLIT + NB_CONV){
        float* xp = sm;
        float* wk = sm2;
        int idx = bx - NB_SPLIT;
        int b = idx / C_, c = idx % C_;
        for (int i=tid;i<1816;i+=256){
            int t = i - FILTR;
            xp[i] = (t>=0 && t<T_) ? ap[b*T_+t] : 0.f;
        }
        for (int i=tid;i<KW+7;i+=256) wk[i] = (i<KW) ? cw[c*KW + i] : 0.f;
        __syncthreads();
        float m = 0.f;
        if (tid < 200){
            int t0 = tid*8;
            float x0=xp[t0],x1=xp[t0+1],x2=xp[t0+2],x3=xp[t0+3];
            float x4=xp[t0+4],x5=xp[t0+5],x6=xp[t0+6],x7=xp[t0+7];
            float a0=0.f,a1=0.f,a2=0.f,a3=0.f,a4=0.f,a5=0.f,a6=0.f,a7=0.f;
            #pragma unroll 4
            for (int k=0;k<KW;k++){
                float w = wk[k];
                a0 = fmaf(x0,w,a0); a1 = fmaf(x1,w,a1);
                a2 = fmaf(x2,w,a2); a3 = fmaf(x3,w,a3);
                a4 = fmaf(x4,w,a4); a5 = fmaf(x5,w,a5);
                a6 = fmaf(x6,w,a6); a7 = fmaf(x7,w,a7);
                x0=x1; x1=x2; x2=x3; x3=x4; x4=x5; x5=x6; x6=x7;
                x7 = xp[t0+k+8];
            }
            m = fmaxf(fmaxf(fmaxf(a0,a1),fmaxf(a2,a3)), fmaxf(fmaxf(a4,a5),fmaxf(a6,a7)));
        }
        red[tid]=m; __syncthreads();
        for (int s=128;s>0;s>>=1){ if (tid<s) red[tid]=fmaxf(red[tid],red[tid+s]); __syncthreads(); }
        if (tid==0) g_feat[b*C_+c] = red[0];
    } else {
        float* s_h = sm;
        float* s_z = sm + 512;
        int idx = bx - NB_SPLIT - NB_CONV;
        int b = idx / 20, j = idx % 20;
        int lane = tid & 31, wp = tid >> 5;
        s_h[tid]     = att_h[b*A_+tid];
        s_h[tid+256] = att_h[b*A_+tid+256];
        s_z[tid]     = dec_z[b*D_+tid];
        s_z[tid+256] = dec_z[b*D_+tid+256];
        s_z[tid+512] = dec_z[b*D_+tid+512];
        s_z[tid+768] = dec_z[b*D_+tid+768];
        __syncthreads();
        int rbase = j*128 + wp*16;
        #pragma unroll 1
        for (int i=0;i<16;i++){
            int r = rbase + i;
            float acc = 0.f;
            if (r < 4*A_){
                const float* wr = &W_hh[(size_t)r*A_];
                #pragma unroll
                for (int k=0;k<16;k++) acc = fmaf(wr[lane+32*k], s_h[lane+32*k], acc);
                #pragma unroll
                for (int o=16;o>0;o>>=1) acc += __shfl_xor_sync(0xffffffffu, acc, o);
                if (lane==0) g_gates[b*4*A_ + r] = acc;
            } else {
                int rd = r - 4*A_;
                const float* wr = &W_dec[(size_t)rd*D_];
                #pragma unroll
                for (int k=0;k<32;k++) acc = fmaf(wr[lane+32*k], s_z[lane+32*k], acc);
                #pragma unroll
                for (int o=16;o>0;o>>=1) acc += __shfl_xor_sync(0xffffffffu, acc, o);
                if (lane==0) g_dp[b*A_ + rd] = acc;
            }
        }
    }
}

// ---------------------------------------------------------------------------
// HMMA score kernel, fp16 2-term: D = Ah*Bh + Al*Bh. 256 threads = 8 warps
// (4m x 2n), warp tile 32x64. KC=32, 3-stage, 2 CTAs/SM, one barrier/kt.
// ---------------------------------------------------------------------------
__global__ void __launch_bounds__(256, 2) score_kernel(
    const float* __restrict__ Wg,
    const float* __restrict__ att_c, const float* __restrict__ b_enc,
    const float* __restrict__ W_ih)
{
    extern __shared__ char smemc[];
    __shared__ float s_sv[NT];
    __shared__ float s_wg[NT];
    const uint32_t sb0 = smem_u32(smemc);
    const int tid = threadIdx.x;
    const int lane = tid & 31, wid = tid >> 5;
    const int warp_m = wid >> 1, warp_n = wid & 1;
    const int b  = blockIdx.z;
    const int t0 = blockIdx.y * MT;
    const int a0 = blockIdx.x * NT;

    if (tid < NT){
        int a = a0 + tid;
        float fe[C_];
        #pragma unroll
        for (int k=0;k<C_;k++) fe[k] = g_feat[b*C_+k];
        float ig = g_gates[b*4*A_ + a]        + gate_corr(W_ih, fe, a);
        float fg = g_gates[b*4*A_ + A_ + a]   + gate_corr(W_ih, fe, A_ + a);
        float gg = g_gates[b*4*A_ + 2*A_ + a] + gate_corr(W_ih, fe, 2*A_ + a);
        float og = g_gates[b*4*A_ + 3*A_ + a] + gate_corr(W_ih, fe, 3*A_ + a);
        float cn = sigmf(fg)*att_c[b*A_+a] + sigmf(ig)*tanhf(gg);
        float hn = sigmf(og)*tanhf(cn);
        s_sv[tid] = g_dp[b*A_+a] + hn + b_enc[a];
        s_wg[tid] = Wg[a];
    }

    uint32_t cpo[2];
    const char *pA_h[2], *pA_l[2], *pB_h[2];
    #pragma unroll
    for (int j=0;j<2;j++){
        int idx = j*256 + tid;
        int row = idx >> 2, ch = idx & 3;
        cpo[j] = swz64(row, ch);
        size_t so = (size_t)row*E_ + ch*8;
        pA_h[j] = (const char*)(g_eh + (size_t)(b*T_ + t0)*E_ + so);
        pA_l[j] = (const char*)(g_el + (size_t)(b*T_ + t0)*E_ + so);
        pB_h[j] = (const char*)(g_wh + (size_t)a0*E_ + so);
    }
    uint32_t ld_st = 0;

    auto load_stage = [&](){
        #pragma unroll
        for (int j=0;j<2;j++){
            uint32_t d = sb0 + ld_st + cpo[j];
            cp16(d,          pA_h[j]);
            cp16(d + 8192,   pA_l[j]);
            cp16(d + 16384,  pB_h[j]);
            pA_h[j] += 64; pA_l[j] += 64; pB_h[j] += 64;
        }
        asm volatile("cp.async.commit_group;" ::: "memory");
        ld_st = (ld_st == 2*STAGE_B) ? 0u : ld_st + STAGE_B;
    };

    const int lrow = lane & 15, lsel = lane >> 4;
    const int arow0 = warp_m*32 + lrow, arow1 = arow0 + 16;
    uint32_t ao0[2], ao1[2], bo[4][2];
    #pragma unroll
    for (int k16=0;k16<2;k16++){
        int ch = k16*2 + lsel;
        ao0[k16] = swz64(arow0, ch);
        ao1[k16] = swz64(arow1, ch);
        #pragma unroll
        for (int g=0; g<4; g++)
            bo[g][k16] = swz64(warp_n*64 + g*16 + lrow, ch);
    }

    float acc[2][8][4];
    #pragma unroll
    for (int i=0;i<2;i++)
        #pragma unroll
        for (int j=0;j<8;j++)
            #pragma unroll
            for (int k=0;k<4;k++) acc[i][j][k] = 0.f;

    load_stage();
    load_stage();

    uint32_t st = 0;
    #pragma unroll 1
    for (int kt = 0; kt < NKT; kt++){
        if (kt == NKT-1) asm volatile("cp.async.wait_group 0;" ::: "memory");
        else             asm volatile("cp.async.wait_group 1;" ::: "memory");
        __syncthreads();
        if (kt + 2 < NKT) load_stage();

        const uint32_t base = sb0 + st;
        st = (st == 2*STAGE_B) ? 0u : st + STAGE_B;
        #pragma unroll
        for (int k16=0; k16<2; k16++){
            uint32_t Ah0[4], Ah1[4], Al0[4], Al1[4];
            ldsm4(Ah0, base + ao0[k16]);
            ldsm4(Ah1, base + ao1[k16]);
            ldsm4(Al0, base + 8192 + ao0[k16]);
            ldsm4(Al1, base + 8192 + ao1[k16]);
            #pragma unroll
            for (int g=0; g<4; g++){
                uint32_t Bh[4];
                ldsm4(Bh, base + 16384 + bo[g][k16]);
                mma16816(acc[0][2*g],   Ah0, Bh[0], Bh[2]);
                mma16816(acc[0][2*g+1], Ah0, Bh[1], Bh[3]);
                mma16816(acc[1][2*g],   Ah1, Bh[0], Bh[2]);
                mma16816(acc[1][2*g+1], Ah1, Bh[1], Bh[3]);
                mma16816(acc[0][2*g],   Al0, Bh[0], Bh[2]);
                mma16816(acc[0][2*g+1], Al0, Bh[1], Bh[3]);
                mma16816(acc[1][2*g],   Al1, Bh[0], Bh[2]);
                mma16816(acc[1][2*g+1], Al1, Bh[1], Bh[3]);
            }
        }
    }

    const int qh = lane >> 2, qr = lane & 3;
    #pragma unroll
    for (int mi=0; mi<2; mi++){
        float p0 = 0.f, p1 = 0.f;
        #pragma unroll
        for (int nf=0; nf<8; nf++){
            int a = warp_n*64 + nf*8 + 2*qr;
            const float* c = acc[mi][nf];
            p0 = fmaf(s_wg[a],   tanhf(c[0] + s_sv[a]),   p0);
            p0 = fmaf(s_wg[a+1], tanhf(c[1] + s_sv[a+1]), p0);
            p1 = fmaf(s_wg[a],   tanhf(c[2] + s_sv[a]),   p1);
            p1 = fmaf(s_wg[a+1], tanhf(c[3] + s_sv[a+1]), p1);
        }
        p0 += __shfl_xor_sync(0xffffffffu, p0, 1);
        p0 += __shfl_xor_sync(0xffffffffu, p0, 2);
        p1 += __shfl_xor_sync(0xffffffffu, p1, 1);
        p1 += __shfl_xor_sync(0xffffffffu, p1, 2);
        if (qr == 0){
            int t = t0 + warp_m*32 + mi*16 + qh;
            if (t < T_)     atomicAdd(&g_e[b*T_ + t],     p0);
            if (t+8 < T_)   atomicAdd(&g_e[b*T_ + t + 8], p1);
        }
    }
}

// ---------------------------------------------------------------------------
// masked scaled softmax + LSTM h/c outputs (fused)
// ---------------------------------------------------------------------------
__global__ void softmax_kernel(const int* __restrict__ len,
                               const float* __restrict__ att_c,
                               const float* __restrict__ W_ih,
                               float* __restrict__ out){
    __shared__ float se[T_];
    __shared__ float red[256];
    int b = blockIdx.x, tid = threadIdx.x;
    int L = len[b];
    for (int t=tid;t<T_;t+=256) se[t] = g_e[b*T_+t];
    {
        float fe[C_];
        #pragma unroll
        for (int k=0;k<C_;k++) fe[k] = g_feat[b*C_+k];
        #pragma unroll
        for (int p=0;p<2;p++){
            int a = p*256 + tid;
            float ig = g_gates[b*4*A_ + a]        + gate_corr(W_ih, fe, a);
            float fg = g_gates[b*4*A_ + A_ + a]   + gate_corr(W_ih, fe, A_ + a);
            float gg = g_gates[b*4*A_ + 2*A_ + a] + gate_corr(W_ih, fe, 2*A_ + a);
            float og = g_gates[b*4*A_ + 3*A_ + a] + gate_corr(W_ih, fe, 3*A_ + a);
            float cn = sigmf(fg)*att_c[b*A_+a] + sigmf(ig)*tanhf(gg);
            float hn = sigmf(og)*tanhf(cn);
            out[OUT_H  + b*A_ + a] = hn;
            out[OUT_CN + b*A_ + a] = cn;
        }
    }
    __syncthreads();
    float m = -3.4e38f;
    for (int t=tid;t<L;t+=256) m = fmaxf(m, se[t]);
    red[tid]=m; __syncthreads();
    for (int s=128;s>0;s>>=1){ if (tid<s) red[tid]=fmaxf(red[tid],red[tid+s]); __syncthreads(); }
    m = red[0];
    __syncthreads();
    float sum = 0.f;
    for (int t=tid;t<T_;t+=256){
        float v = (t<L) ? expf(2.0f*(se[t]-m)) : 0.f;
        se[t] = v;
        sum += v;
    }
    red[tid]=sum; __syncthreads();
    for (int s=128;s>0;s>>=1){ if (tid<s) red[tid]+=red[tid+s]; __syncthreads(); }
    float inv = 1.0f/red[0];
    for (int t=tid;t<T_;t+=256) out[OUT_W + b*T_ + t] = se[t]*inv;
}

// ---------------------------------------------------------------------------
// ctx = w @ enc, split over t (8 ways), atomic accumulation, streaming loads
// ---------------------------------------------------------------------------
__global__ void ctx_kernel(const float* __restrict__ enc, float* __restrict__ out){
    __shared__ float sw[200];
    int b = blockIdx.x;
    int ec = blockIdx.y*256 + threadIdx.x;
    int tbase = blockIdx.z * 200;
    if (threadIdx.x < 200) sw[threadIdx.x] = out[OUT_W + b*T_ + tbase + threadIdx.x];
    __syncthreads();
    const float* eb = enc + ((size_t)b*T_ + tbase)*E_ + ec;
    float a0=0.f,a1=0.f,a2=0.f,a3=0.f,a4=0.f,a5=0.f,a6=0.f,a7=0.f;
    #pragma unroll 1
    for (int t=0;t<200;t+=8){
        float e0 = __ldcs(&eb[(size_t)(t+0)*E_]);
        float e1 = __ldcs(&eb[(size_t)(t+1)*E_]);
        float e2 = __ldcs(&eb[(size_t)(t+2)*E_]);
        float e3 = __ldcs(&eb[(size_t)(t+3)*E_]);
        float e4 = __ldcs(&eb[(size_t)(t+4)*E_]);
        float e5 = __ldcs(&eb[(size_t)(t+5)*E_]);
        float e6 = __ldcs(&eb[(size_t)(t+6)*E_]);
        float e7 = __ldcs(&eb[(size_t)(t+7)*E_]);
        a0 = fmaf(sw[t+0], e0, a0);
        a1 = fmaf(sw[t+1], e1, a1);
        a2 = fmaf(sw[t+2], e2, a2);
        a3 = fmaf(sw[t+3], e3, a3);
        a4 = fmaf(sw[t+4], e4, a4);
        a5 = fmaf(sw[t+5], e5, a5);
        a6 = fmaf(sw[t+6], e6, a6);
        a7 = fmaf(sw[t+7], e7, a7);
    }
    atomicAdd(&out[OUT_CTX + b*E_ + ec], ((a0+a1)+(a2+a3)) + ((a4+a5)+(a6+a7)));
}

// ---------------------------------------------------------------------------
extern "C" void kernel_launch(void* const* d_in, const int* in_sizes, int n_in,
                              void* d_out, int out_size)
{
    const float* enc      = (const float*)d_in[0];
    const int*   len      = (const int*)  d_in[1];
    const float* dec_z    = (const float*)d_in[2];
    const float* att_prev = (const float*)d_in[3];
    const float* att_h    = (const float*)d_in[4];
    const float* att_c    = (const float*)d_in[5];
    const float* W_enc    = (const float*)d_in[6];
    const float* b_enc    = (const float*)d_in[7];
    const float* W_dec    = (const float*)d_in[8];
    const float* conv_w   = (const float*)d_in[9];
    const float* W_ih     = (const float*)d_in[10];
    const float* W_hh     = (const float*)d_in[11];
    const float* W_g      = (const float*)d_in[12];
    float* out = (float*)d_out;

    cudaFuncSetAttribute(score_kernel,
                         cudaFuncAttributeMaxDynamicSharedMemorySize, SMEM_DYN);

    mega_pre_kernel<<<NB_SPLIT + NB_CONV + NB_GATES, 256>>>(
        W_enc, enc, att_prev, conv_w, dec_z, att_h, W_dec, W_hh, out);
    score_kernel<<<dim3(A_/NT, MTILES, B_), 256, SMEM_DYN>>>(W_g, att_c, b_enc, W_ih);
    softmax_kernel<<<B_, 256>>>(len, att_c, W_ih, out);
    ctx_kernel<<<dim3(B_, E_/256, 8), 256>>>(enc, out);
}

// round 16
// speedup vs baseline: 2.1269x; 1.4353x over previous
#include <cuda_runtime.h>
#include <cuda_fp16.h>
#include <cstdint>
#include <math.h>

#define B_   32
#define T_   1600
#define E_   1024
#define D_   1024
#define A_   512
#define C_   10
#define KW   201
#define FILTR 100

// output layout: ctx (B,E), w (B,T), h_new (B,A), c_new (B,A)
#define OUT_CTX 0
#define OUT_W   (B_*E_)
#define OUT_H   (OUT_W + B_*T_)
#define OUT_CN  (OUT_H + B_*A_)

// GEMM tiling
#define MT   128
#define NT   128
#define KC   32
#define NKT  (E_/KC)              // 32
#define MTILES ((T_ + MT - 1)/MT) // 13

// dynamic smem: 3 stages x 16KB (Ah 8K | Bh 8K)
#define STAGE_B 16384u
#define SMEM_DYN 49152

// mega_pre block ranges
#define NB_SPLIT 4096
#define NB_CONV  (B_*C_)          // 320
#define NB_GATES 640

// -------- scratch --------
__device__ __half g_eh[(size_t)(B_*T_ + MT) * E_];   // enc fp16 (pad rows 0)
__device__ __half g_wh[(size_t)A_ * E_];             // W_enc fp16
__device__ float g_feat[B_*C_];
__device__ float g_gates[B_*4*A_];   // W_hh@h part only (W_ih@feat added later)
__device__ float g_dp[B_*A_];
__device__ float g_e[B_*T_];

static __device__ __forceinline__ float sigmf(float x){ return 1.0f/(1.0f+expf(-x)); }
static __device__ __forceinline__ unsigned smem_u32(const void* p){
    return (unsigned)__cvta_generic_to_shared(p);
}
static __device__ __forceinline__ void cp16(unsigned d, const void* s){
    asm volatile("cp.async.cg.shared.global [%0], [%1], 16;" :: "r"(d), "l"(s));
}
static __device__ __forceinline__ void ldsm4(uint32_t r[4], uint32_t addr){
    asm volatile("ldmatrix.sync.aligned.m8n8.x4.shared.b16 {%0,%1,%2,%3}, [%4];"
                 : "=r"(r[0]), "=r"(r[1]), "=r"(r[2]), "=r"(r[3]) : "r"(addr));
}
static __device__ __forceinline__ void mma16816(float c[4], const uint32_t a[4],
                                                uint32_t b0, uint32_t b1){
    asm volatile("mma.sync.aligned.m16n8k16.row.col.f32.f16.f16.f32 "
                 "{%0,%1,%2,%3}, {%4,%5,%6,%7}, {%8,%9}, {%0,%1,%2,%3};"
                 : "+f"(c[0]), "+f"(c[1]), "+f"(c[2]), "+f"(c[3])
                 : "r"(a[0]), "r"(a[1]), "r"(a[2]), "r"(a[3]), "r"(b0), "r"(b1));
}
static __device__ __forceinline__ uint32_t swz64(int row, int ch){
    return (uint32_t)row*64 + (uint32_t)(((ch + (row>>1)) & 3) << 4);
}
static __device__ __forceinline__ uint2 round4h(float4 v){
    __half2 p0 = __floats2half2_rn(v.x, v.y);
    __half2 p1 = __floats2half2_rn(v.z, v.w);
    uint2 r;
    r.x = *reinterpret_cast<uint32_t*>(&p0);
    r.y = *reinterpret_cast<uint32_t*>(&p1);
    return r;
}
static __device__ __forceinline__ float gate_corr(const float* W_ih,
                                                  const float* fe, int row){
    const float* wr = W_ih + row*C_;
    float s = 0.f;
    #pragma unroll
    for (int k=0;k<C_;k++) s = fmaf(wr[k], fe[k], s);
    return s;
}
static __device__ __forceinline__ float4 ldcs4(const float4* p){
    float4 v;
    asm("ld.global.cs.v4.f32 {%0,%1,%2,%3}, [%4];"
        : "=f"(v.x), "=f"(v.y), "=f"(v.z), "=f"(v.w) : "l"(p));
    return v;
}

// ---------------------------------------------------------------------------
// mega_pre: [0,4096) enc/W round-to-fp16 + zeroing | conv | gates
// ---------------------------------------------------------------------------
__global__ __launch_bounds__(256) void mega_pre_kernel(
    const float* __restrict__ W, const float* __restrict__ enc,
    const float* __restrict__ ap, const float* __restrict__ cw,
    const float* __restrict__ dec_z, const float* __restrict__ att_h,
    const float* __restrict__ W_dec, const float* __restrict__ W_hh,
    float* __restrict__ out)
{
    __shared__ float sm[2048];
    __shared__ float sm2[1024];
    __shared__ float red[256];
    const int bx = blockIdx.x, tid = threadIdx.x;

    if (bx < NB_SPLIT){
        const int n4e = B_*T_*E_/4;
        const int n4w = A_*E_/4;
        const int stride = NB_SPLIT*256;
        for (int i = bx*256 + tid; i < n4e; i += stride){
            ((uint2*)g_eh)[i] = round4h(ldcs4((const float4*)enc + i));
            if (i < n4w)
                ((uint2*)g_wh)[i] = round4h(((const float4*)W)[i]);
            if (i < B_*T_) g_e[i] = 0.f;
            if (i < B_*E_) out[OUT_CTX + i] = 0.f;
        }
    } else if (bx < NB_SPLIT + NB_CONV){
        float* xp = sm;
        float* wk = sm2;
        int idx = bx - NB_SPLIT;
        int b = idx / C_, c = idx % C_;
        for (int i=tid;i<1816;i+=256){
            int t = i - FILTR;
            xp[i] = (t>=0 && t<T_) ? ap[b*T_+t] : 0.f;
        }
        for (int i=tid;i<KW+7;i+=256) wk[i] = (i<KW) ? cw[c*KW + i] : 0.f;
        __syncthreads();
        float m = 0.f;
        if (tid < 200){
            int t0 = tid*8;
            float x0=xp[t0],x1=xp[t0+1],x2=xp[t0+2],x3=xp[t0+3];
            float x4=xp[t0+4],x5=xp[t0+5],x6=xp[t0+6],x7=xp[t0+7];
            float a0=0.f,a1=0.f,a2=0.f,a3=0.f,a4=0.f,a5=0.f,a6=0.f,a7=0.f;
            #pragma unroll 4
            for (int k=0;k<KW;k++){
                float w = wk[k];
                a0 = fmaf(x0,w,a0); a1 = fmaf(x1,w,a1);
                a2 = fmaf(x2,w,a2); a3 = fmaf(x3,w,a3);
                a4 = fmaf(x4,w,a4); a5 = fmaf(x5,w,a5);
                a6 = fmaf(x6,w,a6); a7 = fmaf(x7,w,a7);
                x0=x1; x1=x2; x2=x3; x3=x4; x4=x5; x5=x6; x6=x7;
                x7 = xp[t0+k+8];
            }
            m = fmaxf(fmaxf(fmaxf(a0,a1),fmaxf(a2,a3)), fmaxf(fmaxf(a4,a5),fmaxf(a6,a7)));
        }
        red[tid]=m; __syncthreads();
        for (int s=128;s>0;s>>=1){ if (tid<s) red[tid]=fmaxf(red[tid],red[tid+s]); __syncthreads(); }
        if (tid==0) g_feat[b*C_+c] = red[0];
    } else {
        float* s_h = sm;
        float* s_z = sm + 512;
        int idx = bx - NB_SPLIT - NB_CONV;
        int b = idx / 20, j = idx % 20;
        int lane = tid & 31, wp = tid >> 5;
        s_h[tid]     = att_h[b*A_+tid];
        s_h[tid+256] = att_h[b*A_+tid+256];
        s_z[tid]     = dec_z[b*D_+tid];
        s_z[tid+256] = dec_z[b*D_+tid+256];
        s_z[tid+512] = dec_z[b*D_+tid+512];
        s_z[tid+768] = dec_z[b*D_+tid+768];
        __syncthreads();
        int rbase = j*128 + wp*16;
        #pragma unroll 1
        for (int i=0;i<16;i++){
            int r = rbase + i;
            float acc = 0.f;
            if (r < 4*A_){
                const float* wr = &W_hh[(size_t)r*A_];
                #pragma unroll
                for (int k=0;k<16;k++) acc = fmaf(wr[lane+32*k], s_h[lane+32*k], acc);
                #pragma unroll
                for (int o=16;o>0;o>>=1) acc += __shfl_xor_sync(0xffffffffu, acc, o);
                if (lane==0) g_gates[b*4*A_ + r] = acc;
            } else {
                int rd = r - 4*A_;
                const float* wr = &W_dec[(size_t)rd*D_];
                #pragma unroll
                for (int k=0;k<32;k++) acc = fmaf(wr[lane+32*k], s_z[lane+32*k], acc);
                #pragma unroll
                for (int o=16;o>0;o>>=1) acc += __shfl_xor_sync(0xffffffffu, acc, o);
                if (lane==0) g_dp[b*A_ + rd] = acc;
            }
        }
    }
}

// ---------------------------------------------------------------------------
// HMMA score kernel, fp16 1-term: D = Ah*Bh. 256 threads = 8 warps (4m x 2n),
// warp tile 32x64. KC=32, 3-stage, 2 CTAs/SM, one barrier/kt.
// ---------------------------------------------------------------------------
__global__ void __launch_bounds__(256, 2) score_kernel(
    const float* __restrict__ Wg,
    const float* __restrict__ att_c, const float* __restrict__ b_enc,
    const float* __restrict__ W_ih)
{
    extern __shared__ char smemc[];
    __shared__ float s_sv[NT];
    __shared__ float s_wg[NT];
    const uint32_t sb0 = smem_u32(smemc);
    const int tid = threadIdx.x;
    const int lane = tid & 31, wid = tid >> 5;
    const int warp_m = wid >> 1, warp_n = wid & 1;
    const int b  = blockIdx.z;
    const int t0 = blockIdx.y * MT;
    const int a0 = blockIdx.x * NT;

    if (tid < NT){
        int a = a0 + tid;
        float fe[C_];
        #pragma unroll
        for (int k=0;k<C_;k++) fe[k] = g_feat[b*C_+k];
        float ig = g_gates[b*4*A_ + a]        + gate_corr(W_ih, fe, a);
        float fg = g_gates[b*4*A_ + A_ + a]   + gate_corr(W_ih, fe, A_ + a);
        float gg = g_gates[b*4*A_ + 2*A_ + a] + gate_corr(W_ih, fe, 2*A_ + a);
        float og = g_gates[b*4*A_ + 3*A_ + a] + gate_corr(W_ih, fe, 3*A_ + a);
        float cn = sigmf(fg)*att_c[b*A_+a] + sigmf(ig)*tanhf(gg);
        float hn = sigmf(og)*tanhf(cn);
        s_sv[tid] = g_dp[b*A_+a] + hn + b_enc[a];
        s_wg[tid] = Wg[a];
    }

    uint32_t cpo[2];
    const char *pA_h[2], *pB_h[2];
    #pragma unroll
    for (int j=0;j<2;j++){
        int idx = j*256 + tid;
        int row = idx >> 2, ch = idx & 3;
        cpo[j] = swz64(row, ch);
        size_t so = (size_t)row*E_ + ch*8;
        pA_h[j] = (const char*)(g_eh + (size_t)(b*T_ + t0)*E_ + so);
        pB_h[j] = (const char*)(g_wh + (size_t)a0*E_ + so);
    }
    uint32_t ld_st = 0;

    auto load_stage = [&](){
        #pragma unroll
        for (int j=0;j<2;j++){
            uint32_t d = sb0 + ld_st + cpo[j];
            cp16(d,        pA_h[j]);
            cp16(d + 8192, pB_h[j]);
            pA_h[j] += 64; pB_h[j] += 64;
        }
        asm volatile("cp.async.commit_group;" ::: "memory");
        ld_st = (ld_st == 2*STAGE_B) ? 0u : ld_st + STAGE_B;
    };

    const int lrow = lane & 15, lsel = lane >> 4;
    const int arow0 = warp_m*32 + lrow, arow1 = arow0 + 16;
    uint32_t ao0[2], ao1[2], bo[4][2];
    #pragma unroll
    for (int k16=0;k16<2;k16++){
        int ch = k16*2 + lsel;
        ao0[k16] = swz64(arow0, ch);
        ao1[k16] = swz64(arow1, ch);
        #pragma unroll
        for (int g=0; g<4; g++)
            bo[g][k16] = swz64(warp_n*64 + g*16 + lrow, ch);
    }

    float acc[2][8][4];
    #pragma unroll
    for (int i=0;i<2;i++)
        #pragma unroll
        for (int j=0;j<8;j++)
            #pragma unroll
            for (int k=0;k<4;k++) acc[i][j][k] = 0.f;

    load_stage();
    load_stage();

    uint32_t st = 0;
    #pragma unroll 1
    for (int kt = 0; kt < NKT; kt++){
        if (kt == NKT-1) asm volatile("cp.async.wait_group 0;" ::: "memory");
        else             asm volatile("cp.async.wait_group 1;" ::: "memory");
        __syncthreads();
        if (kt + 2 < NKT) load_stage();

        const uint32_t base = sb0 + st;
        st = (st == 2*STAGE_B) ? 0u : st + STAGE_B;
        #pragma unroll
        for (int k16=0; k16<2; k16++){
            uint32_t Ah0[4], Ah1[4];
            ldsm4(Ah0, base + ao0[k16]);
            ldsm4(Ah1, base + ao1[k16]);
            #pragma unroll
            for (int g=0; g<4; g++){
                uint32_t Bh[4];
                ldsm4(Bh, base + 8192 + bo[g][k16]);
                mma16816(acc[0][2*g],   Ah0, Bh[0], Bh[2]);
                mma16816(acc[0][2*g+1], Ah0, Bh[1], Bh[3]);
                mma16816(acc[1][2*g],   Ah1, Bh[0], Bh[2]);
                mma16816(acc[1][2*g+1], Ah1, Bh[1], Bh[3]);
            }
        }
    }

    const int qh = lane >> 2, qr = lane & 3;
    #pragma unroll
    for (int mi=0; mi<2; mi++){
        float p0 = 0.f, p1 = 0.f;
        #pragma unroll
        for (int nf=0; nf<8; nf++){
            int a = warp_n*64 + nf*8 + 2*qr;
            const float* c = acc[mi][nf];
            p0 = fmaf(s_wg[a],   tanhf(c[0] + s_sv[a]),   p0);
            p0 = fmaf(s_wg[a+1], tanhf(c[1] + s_sv[a+1]), p0);
            p1 = fmaf(s_wg[a],   tanhf(c[2] + s_sv[a]),   p1);
            p1 = fmaf(s_wg[a+1], tanhf(c[3] + s_sv[a+1]), p1);
        }
        p0 += __shfl_xor_sync(0xffffffffu, p0, 1);
        p0 += __shfl_xor_sync(0xffffffffu, p0, 2);
        p1 += __shfl_xor_sync(0xffffffffu, p1, 1);
        p1 += __shfl_xor_sync(0xffffffffu, p1, 2);
        if (qr == 0){
            int t = t0 + warp_m*32 + mi*16 + qh;
            if (t < T_)     atomicAdd(&g_e[b*T_ + t],     p0);
            if (t+8 < T_)   atomicAdd(&g_e[b*T_ + t + 8], p1);
        }
    }
}

// ---------------------------------------------------------------------------
// masked scaled softmax + LSTM h/c outputs (fused)
// ---------------------------------------------------------------------------
__global__ void softmax_kernel(const int* __restrict__ len,
                               const float* __restrict__ att_c,
                               const float* __restrict__ W_ih,
                               float* __restrict__ out){
    __shared__ float se[T_];
    __shared__ float red[256];
    int b = blockIdx.x, tid = threadIdx.x;
    int L = len[b];
    for (int t=tid;t<T_;t+=256) se[t] = g_e[b*T_+t];
    {
        float fe[C_];
        #pragma unroll
        for (int k=0;k<C_;k++) fe[k] = g_feat[b*C_+k];
        #pragma unroll
        for (int p=0;p<2;p++){
            int a = p*256 + tid;
            float ig = g_gates[b*4*A_ + a]        + gate_corr(W_ih, fe, a);
            float fg = g_gates[b*4*A_ + A_ + a]   + gate_corr(W_ih, fe, A_ + a);
            float gg = g_gates[b*4*A_ + 2*A_ + a] + gate_corr(W_ih, fe, 2*A_ + a);
            float og = g_gates[b*4*A_ + 3*A_ + a] + gate_corr(W_ih, fe, 3*A_ + a);
            float cn = sigmf(fg)*att_c[b*A_+a] + sigmf(ig)*tanhf(gg);
            float hn = sigmf(og)*tanhf(cn);
            out[OUT_H  + b*A_ + a] = hn;
            out[OUT_CN + b*A_ + a] = cn;
        }
    }
    __syncthreads();
    float m = -3.4e38f;
    for (int t=tid;t<L;t+=256) m = fmaxf(m, se[t]);
    red[tid]=m; __syncthreads();
    for (int s=128;s>0;s>>=1){ if (tid<s) red[tid]=fmaxf(red[tid],red[tid+s]); __syncthreads(); }
    m = red[0];
    __syncthreads();
    float sum = 0.f;
    for (int t=tid;t<T_;t+=256){
        float v = (t<L) ? expf(2.0f*(se[t]-m)) : 0.f;
        se[t] = v;
        sum += v;
    }
    red[tid]=sum; __syncthreads();
    for (int s=128;s>0;s>>=1){ if (tid<s) red[tid]+=red[tid+s]; __syncthreads(); }
    float inv = 1.0f/red[0];
    for (int t=tid;t<T_;t+=256) out[OUT_W + b*T_ + t] = se[t]*inv;
}

// ---------------------------------------------------------------------------
// ctx = w @ enc, split over t (8 ways), atomic accumulation, streaming loads
// ---------------------------------------------------------------------------
__global__ void ctx_kernel(const float* __restrict__ enc, float* __restrict__ out){
    __shared__ float sw[200];
    int b = blockIdx.x;
    int ec = blockIdx.y*256 + threadIdx.x;
    int tbase = blockIdx.z * 200;
    if (threadIdx.x < 200) sw[threadIdx.x] = out[OUT_W + b*T_ + tbase + threadIdx.x];
    __syncthreads();
    const float* eb = enc + ((size_t)b*T_ + tbase)*E_ + ec;
    float a0=0.f,a1=0.f,a2=0.f,a3=0.f,a4=0.f,a5=0.f,a6=0.f,a7=0.f;
    #pragma unroll 1
    for (int t=0;t<200;t+=8){
        float e0 = __ldcs(&eb[(size_t)(t+0)*E_]);
        float e1 = __ldcs(&eb[(size_t)(t+1)*E_]);
        float e2 = __ldcs(&eb[(size_t)(t+2)*E_]);
        float e3 = __ldcs(&eb[(size_t)(t+3)*E_]);
        float e4 = __ldcs(&eb[(size_t)(t+4)*E_]);
        float e5 = __ldcs(&eb[(size_t)(t+5)*E_]);
        float e6 = __ldcs(&eb[(size_t)(t+6)*E_]);
        float e7 = __ldcs(&eb[(size_t)(t+7)*E_]);
        a0 = fmaf(sw[t+0], e0, a0);
        a1 = fmaf(sw[t+1], e1, a1);
        a2 = fmaf(sw[t+2], e2, a2);
        a3 = fmaf(sw[t+3], e3, a3);
        a4 = fmaf(sw[t+4], e4, a4);
        a5 = fmaf(sw[t+5], e5, a5);
        a6 = fmaf(sw[t+6], e6, a6);
        a7 = fmaf(sw[t+7], e7, a7);
    }
    atomicAdd(&out[OUT_CTX + b*E_ + ec], ((a0+a1)+(a2+a3)) + ((a4+a5)+(a6+a7)));
}

// ---------------------------------------------------------------------------
extern "C" void kernel_launch(void* const* d_in, const int* in_sizes, int n_in,
                              void* d_out, int out_size)
{
    const float* enc      = (const float*)d_in[0];
    const int*   len      = (const int*)  d_in[1];
    const float* dec_z    = (const float*)d_in[2];
    const float* att_prev = (const float*)d_in[3];
    const float* att_h    = (const float*)d_in[4];
    const float* att_c    = (const float*)d_in[5];
    const float* W_enc    = (const float*)d_in[6];
    const float* b_enc    = (const float*)d_in[7];
    const float* W_dec    = (const float*)d_in[8];
    const float* conv_w   = (const float*)d_in[9];
    const float* W_ih     = (const float*)d_in[10];
    const float* W_hh     = (const float*)d_in[11];
    const float* W_g      = (const float*)d_in[12];
    float* out = (float*)d_out;

    cudaFuncSetAttribute(score_kernel,
                         cudaFuncAttributeMaxDynamicSharedMemorySize, SMEM_DYN);

    mega_pre_kernel<<<NB_SPLIT + NB_CONV + NB_GATES, 256>>>(
        W_enc, enc, att_prev, conv_w, dec_z, att_h, W_dec, W_hh, out);
    score_kernel<<<dim3(A_/NT, MTILES, B_), 256, SMEM_DYN>>>(W_g, att_c, b_enc, W_ih);
    softmax_kernel<<<B_, 256>>>(len, att_c, W_ih, out);
    ctx_kernel<<<dim3(B_, E_/256, 8), 256>>>(enc, out);
}